// round 11
// baseline (speedup 1.0000x reference)
#include <cuda_runtime.h>
#include <cuda_bf16.h>
#include <cuda_pipeline.h>
#include <mma.h>
#include <cstdint>

using namespace nvcuda;

#define NN 100000
#define NE 1600000
#define DD 128
#define KK 256   // concat K: [mean | h]

// ---------------- static device scratch (~167MB, proven-safe envelope) ----------
__device__ __nv_bfloat16 g_mh[(size_t)NN * DD];   // mean hi
__device__ __nv_bfloat16 g_ml[(size_t)NN * DD];   // mean lo
__device__ __nv_bfloat16 g_xh0[(size_t)NN * DD];  // activation split, set 0
__device__ __nv_bfloat16 g_xl0[(size_t)NN * DD];
__device__ __nv_bfloat16 g_xh1[(size_t)NN * DD];  // activation split, set 1
__device__ __nv_bfloat16 g_xl1[(size_t)NN * DD];
__device__ __nv_bfloat16 g_Whi[3 * KK * DD];      // concat weights hi
__device__ __nv_bfloat16 g_Wlo[3 * KK * DD];      // concat weights lo
// CSR (g_cnt statically zero-initialized; scan_kernel re-zeros it each launch)
__device__ int g_cnt[NN];
__device__ int g_rowptr[NN + 1];
__device__ int g_cursor[NN];
__device__ int g_csrc[NE];

// ---------------- helpers ----------------
__device__ __forceinline__ void split4(const float4 v, uint2* ph, uint2* pl) {
    __nv_bfloat162 h01, h23, l01, l23;
    h01.x = __float2bfloat16_rn(v.x); h01.y = __float2bfloat16_rn(v.y);
    h23.x = __float2bfloat16_rn(v.z); h23.y = __float2bfloat16_rn(v.w);
    l01.x = __float2bfloat16_rn(v.x - __bfloat162float(h01.x));
    l01.y = __float2bfloat16_rn(v.y - __bfloat162float(h01.y));
    l23.x = __float2bfloat16_rn(v.z - __bfloat162float(h23.x));
    l23.y = __float2bfloat16_rn(v.w - __bfloat162float(h23.y));
    uint2 h, l;
    h.x = *reinterpret_cast<unsigned*>(&h01); h.y = *reinterpret_cast<unsigned*>(&h23);
    l.x = *reinterpret_cast<unsigned*>(&l01); l.y = *reinterpret_cast<unsigned*>(&l23);
    *ph = h; *pl = l;
}

// reconstruct 4 f32 from split bf16 hi/lo arrays at element offset off
__device__ __forceinline__ float4 ld_split4(const __nv_bfloat16* XH,
                                            const __nv_bfloat16* XL, size_t off) {
    uint2 h = *reinterpret_cast<const uint2*>(XH + off);
    uint2 l = *reinterpret_cast<const uint2*>(XL + off);
    float2 fh01 = __bfloat1622float2(*reinterpret_cast<__nv_bfloat162*>(&h.x));
    float2 fh23 = __bfloat1622float2(*reinterpret_cast<__nv_bfloat162*>(&h.y));
    float2 fl01 = __bfloat1622float2(*reinterpret_cast<__nv_bfloat162*>(&l.x));
    float2 fl23 = __bfloat1622float2(*reinterpret_cast<__nv_bfloat162*>(&l.y));
    return make_float4(fh01.x + fl01.x, fh01.y + fl01.y,
                       fh23.x + fl23.x, fh23.y + fl23.y);
}

// ---------------- combined conversion: weights + input x -> split set 0 --------
__global__ void convert_all_kernel(const float* __restrict__ Wl,
                                   const float* __restrict__ Wr,
                                   const float* __restrict__ x) {
    int idx = blockIdx.x * blockDim.x + threadIdx.x;
    const int nw = 3 * KK * DD;
    if (idx < nw) {
        int l = idx / (KK * DD);
        int r = idx - l * (KK * DD);
        int k = r / DD;
        int n = r - k * DD;
        float v = (k < DD) ? Wl[(size_t)l * DD * DD + k * DD + n]
                           : Wr[(size_t)l * DD * DD + (k - DD) * DD + n];
        __nv_bfloat16 hi = __float2bfloat16_rn(v);
        g_Whi[idx] = hi;
        g_Wlo[idx] = __float2bfloat16_rn(v - __bfloat162float(hi));
    }
    size_t n4 = (size_t)NN * DD / 4;
    size_t stride = (size_t)gridDim.x * blockDim.x;
    for (size_t v = (size_t)idx; v < n4; v += stride) {
        float4 f = reinterpret_cast<const float4*>(x)[v];
        split4(f, reinterpret_cast<uint2*>(g_xh0) + v,
                  reinterpret_cast<uint2*>(g_xl0) + v);
    }
}

// ---------------- CSR build ----------------
__global__ void hist_kernel(const int* __restrict__ dst) {
    int stride = gridDim.x * blockDim.x;
    for (int e = blockIdx.x * blockDim.x + threadIdx.x; e < NE; e += stride)
        atomicAdd(&g_cnt[dst[e]], 1);
}

__global__ void scan_kernel() {
    __shared__ int sh[1024];
    const int t = threadIdx.x;
    const int chunk = (NN + 1023) / 1024;   // 98
    int start = t * chunk;
    int end   = min(start + chunk, NN);
    int s = 0;
    for (int j = start; j < end; j++) {
        g_rowptr[j] = s;
        s += g_cnt[j];
        g_cnt[j] = 0;        // restore for next launch
    }
    sh[t] = s;
    __syncthreads();
    for (int off = 1; off < 1024; off <<= 1) {
        int v = (t >= off) ? sh[t - off] : 0;
        __syncthreads();
        sh[t] += v;
        __syncthreads();
    }
    int excl = (t == 0) ? 0 : sh[t - 1];
    for (int j = start; j < end; j++) {
        int v = g_rowptr[j] + excl;
        g_rowptr[j] = v;
        g_cursor[j] = v;
    }
    if (t == 0) g_rowptr[NN] = NE;
}

__global__ void fill_kernel(const int* __restrict__ src, const int* __restrict__ dst) {
    int stride = gridDim.x * blockDim.x;
    for (int e = blockIdx.x * blockDim.x + threadIdx.x; e < NE; e += stride) {
        int p = atomicAdd(&g_cursor[dst[e]], 1);
        g_csrc[p] = src[e];
    }
}

// ---------------- gather (layer 0): f32 x input, MLP-4 unrolled ---------------
__global__ void gather_f32_kernel(const float* __restrict__ x) {
    int n = (blockIdx.x * blockDim.x + threadIdx.x) >> 5;
    if (n >= NN) return;
    int lane = threadIdx.x & 31;
    int beg = g_rowptr[n];
    int end = g_rowptr[n + 1];
    float4 a0 = make_float4(0.f, 0.f, 0.f, 0.f);
    float4 a1 = make_float4(0.f, 0.f, 0.f, 0.f);
    float4 a2 = make_float4(0.f, 0.f, 0.f, 0.f);
    float4 a3 = make_float4(0.f, 0.f, 0.f, 0.f);
    int e = beg;
    for (; e + 4 <= end; e += 4) {
        int s0 = __ldg(&g_csrc[e + 0]);
        int s1 = __ldg(&g_csrc[e + 1]);
        int s2 = __ldg(&g_csrc[e + 2]);
        int s3 = __ldg(&g_csrc[e + 3]);
        float4 v0 = *reinterpret_cast<const float4*>(x + (size_t)s0 * DD + lane * 4);
        float4 v1 = *reinterpret_cast<const float4*>(x + (size_t)s1 * DD + lane * 4);
        float4 v2 = *reinterpret_cast<const float4*>(x + (size_t)s2 * DD + lane * 4);
        float4 v3 = *reinterpret_cast<const float4*>(x + (size_t)s3 * DD + lane * 4);
        a0.x += v0.x; a0.y += v0.y; a0.z += v0.z; a0.w += v0.w;
        a1.x += v1.x; a1.y += v1.y; a1.z += v1.z; a1.w += v1.w;
        a2.x += v2.x; a2.y += v2.y; a2.z += v2.z; a2.w += v2.w;
        a3.x += v3.x; a3.y += v3.y; a3.z += v3.z; a3.w += v3.w;
    }
    for (; e < end; e++) {
        int s = __ldg(&g_csrc[e]);
        float4 v = *reinterpret_cast<const float4*>(x + (size_t)s * DD + lane * 4);
        a0.x += v.x; a0.y += v.y; a0.z += v.z; a0.w += v.w;
    }
    float4 a;
    a.x = (a0.x + a1.x) + (a2.x + a3.x);
    a.y = (a0.y + a1.y) + (a2.y + a3.y);
    a.z = (a0.z + a1.z) + (a2.z + a3.z);
    a.w = (a0.w + a1.w) + (a2.w + a3.w);
    float invd = 1.f / fmaxf((float)(end - beg), 1.f);
    a.x *= invd; a.y *= invd; a.z *= invd; a.w *= invd;
    size_t o = ((size_t)n * DD + lane * 4) / 4;
    split4(a, reinterpret_cast<uint2*>(g_mh) + o, reinterpret_cast<uint2*>(g_ml) + o);
}

// ---------------- gather (layers 1,2): split bf16 input -----------------------
__global__ void gather_bf16_kernel(int sel) {
    const __nv_bfloat16* XH = sel ? g_xh1 : g_xh0;
    const __nv_bfloat16* XL = sel ? g_xl1 : g_xl0;
    int n = (blockIdx.x * blockDim.x + threadIdx.x) >> 5;
    if (n >= NN) return;
    int lane = threadIdx.x & 31;
    int beg = g_rowptr[n];
    int end = g_rowptr[n + 1];
    float4 a0 = make_float4(0.f, 0.f, 0.f, 0.f);
    float4 a1 = make_float4(0.f, 0.f, 0.f, 0.f);
    float4 a2 = make_float4(0.f, 0.f, 0.f, 0.f);
    float4 a3 = make_float4(0.f, 0.f, 0.f, 0.f);
    int e = beg;
    for (; e + 4 <= end; e += 4) {
        int s0 = __ldg(&g_csrc[e + 0]);
        int s1 = __ldg(&g_csrc[e + 1]);
        int s2 = __ldg(&g_csrc[e + 2]);
        int s3 = __ldg(&g_csrc[e + 3]);
        float4 v0 = ld_split4(XH, XL, (size_t)s0 * DD + lane * 4);
        float4 v1 = ld_split4(XH, XL, (size_t)s1 * DD + lane * 4);
        float4 v2 = ld_split4(XH, XL, (size_t)s2 * DD + lane * 4);
        float4 v3 = ld_split4(XH, XL, (size_t)s3 * DD + lane * 4);
        a0.x += v0.x; a0.y += v0.y; a0.z += v0.z; a0.w += v0.w;
        a1.x += v1.x; a1.y += v1.y; a1.z += v1.z; a1.w += v1.w;
        a2.x += v2.x; a2.y += v2.y; a2.z += v2.z; a2.w += v2.w;
        a3.x += v3.x; a3.y += v3.y; a3.z += v3.z; a3.w += v3.w;
    }
    for (; e < end; e++) {
        int s = __ldg(&g_csrc[e]);
        float4 v = ld_split4(XH, XL, (size_t)s * DD + lane * 4);
        a0.x += v.x; a0.y += v.y; a0.z += v.z; a0.w += v.w;
    }
    float4 a;
    a.x = (a0.x + a1.x) + (a2.x + a3.x);
    a.y = (a0.y + a1.y) + (a2.y + a3.y);
    a.z = (a0.z + a1.z) + (a2.z + a3.z);
    a.w = (a0.w + a1.w) + (a2.w + a3.w);
    float invd = 1.f / fmaxf((float)(end - beg), 1.f);
    a.x *= invd; a.y *= invd; a.z *= invd; a.w *= invd;
    size_t o = ((size_t)n * DD + lane * 4) / 4;
    split4(a, reinterpret_cast<uint2*>(g_mh) + o, reinterpret_cast<uint2*>(g_ml) + o);
}

// ---------------- tensor-core GEMM: cp.async 2-stage pipeline -----------------
// Block 128x128, K=256, BK=16, double-buffered smem, 8 warps as 2(m)x4(n).
#define ALD2 24
#define BLD2 136
#define ST_A (128 * ALD2 * 2)              // 6144 B per A array per stage
#define ST_B (16 * BLD2 * 2)               // 4352 B per B array per stage
#define STAGE_BYTES (2 * ST_A + 2 * ST_B)  // 20992
#define GSM_TOT (2 * STAGE_BYTES)          // 41984 (>= 64*132*4 epilogue stage)
#define STG_LD 132

__global__ __launch_bounds__(256, 2)
void sage_wmma_kernel(float* __restrict__ oout,
                      const float* __restrict__ bias,
                      int lw, int rsel, int wsel, int do_relu, int f32out) {
    const __nv_bfloat16* XH = rsel ? g_xh1 : g_xh0;
    const __nv_bfloat16* XL = rsel ? g_xl1 : g_xl0;
    __nv_bfloat16* WXH = (wsel == 1) ? g_xh1 : g_xh0;
    __nv_bfloat16* WXL = (wsel == 1) ? g_xl1 : g_xl0;

    __shared__ __align__(16) char smem[GSM_TOT];
    float* stage = reinterpret_cast<float*>(smem);   // epilogue alias [64][132]

    const int tid = threadIdx.x;
    const int w  = tid >> 5;
    const int wm = w >> 2;              // 0..1 : 64-row group
    const int wn = w & 3;               // 0..3 : 32-col group
    const int rowBase = blockIdx.x * 128;

    // A copy coords: 2 threads per row, 8 bf16 (16B) each
    const int arow = tid >> 1;                       // 0..127
    const int ach  = (tid & 1) * 8;                  // 0 or 8
    const int aclamp = min(rowBase + arow, NN - 1);  // clamp; extra rows discarded
    // B copy coords: 16 threads per k-row, 8 bf16 each
    const int bkr = tid >> 4;           // 0..15
    const int bch = (tid & 15) * 8;     // 0..120

    wmma::fragment<wmma::accumulator, 16, 16, 16, float> acc[4][2];
    #pragma unroll
    for (int i = 0; i < 4; i++)
        #pragma unroll
        for (int j = 0; j < 2; j++) wmma::fill_fragment(acc[i][j], 0.f);

    auto copy_stage = [&](int kb, int b) {
        char* base = smem + b * STAGE_BYTES;
        __nv_bfloat16* AhiS = reinterpret_cast<__nv_bfloat16*>(base);
        __nv_bfloat16* AloS = reinterpret_cast<__nv_bfloat16*>(base + ST_A);
        __nv_bfloat16* BhiS = reinterpret_cast<__nv_bfloat16*>(base + 2 * ST_A);
        __nv_bfloat16* BloS = reinterpret_cast<__nv_bfloat16*>(base + 2 * ST_A + ST_B);
        const __nv_bfloat16* AH = (kb < 8) ? g_mh : XH;
        const __nv_bfloat16* AL = (kb < 8) ? g_ml : XL;
        size_t ago = (size_t)aclamp * DD + (kb & 7) * 16 + ach;
        __pipeline_memcpy_async(AhiS + arow * ALD2 + ach, AH + ago, 16);
        __pipeline_memcpy_async(AloS + arow * ALD2 + ach, AL + ago, 16);
        size_t bgo = (size_t)lw + (size_t)(kb * 16 + bkr) * DD + bch;
        __pipeline_memcpy_async(BhiS + bkr * BLD2 + bch, g_Whi + bgo, 16);
        __pipeline_memcpy_async(BloS + bkr * BLD2 + bch, g_Wlo + bgo, 16);
    };

    copy_stage(0, 0);
    __pipeline_commit();

    for (int kb = 0; kb < 16; kb++) {
        if (kb < 15) {
            copy_stage(kb + 1, (kb + 1) & 1);
            __pipeline_commit();
            __pipeline_wait_prior(1);   // stage kb complete
        } else {
            __pipeline_wait_prior(0);
        }
        __syncthreads();

        char* base = smem + (kb & 1) * STAGE_BYTES;
        __nv_bfloat16* AhiS = reinterpret_cast<__nv_bfloat16*>(base);
        __nv_bfloat16* AloS = reinterpret_cast<__nv_bfloat16*>(base + ST_A);
        __nv_bfloat16* BhiS = reinterpret_cast<__nv_bfloat16*>(base + 2 * ST_A);
        __nv_bfloat16* BloS = reinterpret_cast<__nv_bfloat16*>(base + 2 * ST_A + ST_B);

        wmma::fragment<wmma::matrix_b, 16, 16, 16, __nv_bfloat16, wmma::row_major> bh[2], bl[2];
        #pragma unroll
        for (int j = 0; j < 2; j++) {
            wmma::load_matrix_sync(bh[j], BhiS + wn * 32 + j * 16, BLD2);
            wmma::load_matrix_sync(bl[j], BloS + wn * 32 + j * 16, BLD2);
        }
        #pragma unroll
        for (int i = 0; i < 4; i++) {
            wmma::fragment<wmma::matrix_a, 16, 16, 16, __nv_bfloat16, wmma::row_major> ah, al;
            wmma::load_matrix_sync(ah, AhiS + (wm * 64 + i * 16) * ALD2, ALD2);
            wmma::load_matrix_sync(al, AloS + (wm * 64 + i * 16) * ALD2, ALD2);
            #pragma unroll
            for (int j = 0; j < 2; j++) {
                wmma::mma_sync(acc[i][j], ah, bh[j], acc[i][j]);
                wmma::mma_sync(acc[i][j], ah, bl[j], acc[i][j]);
                wmma::mma_sync(acc[i][j], al, bh[j], acc[i][j]);
            }
        }
        __syncthreads();
    }

    // ---- epilogue in two 64-row halves (stage aliases the tile smem) ----
    #pragma unroll
    for (int ph = 0; ph < 2; ph++) {
        if (wm == ph) {
            #pragma unroll
            for (int i = 0; i < 4; i++)
                #pragma unroll
                for (int j = 0; j < 2; j++)
                    wmma::store_matrix_sync(stage + (i * 16) * STG_LD + wn * 32 + j * 16,
                                            acc[i][j], STG_LD, wmma::mem_row_major);
        }
        __syncthreads();
        #pragma unroll
        for (int it = 0; it < 8; it++) {
            int idx = it * 256 + tid;          // 0..2047
            int row = idx >> 5;                // 0..63
            int c4  = (idx & 31) * 4;          // 0..124
            int grow = rowBase + ph * 64 + row;
            if (grow < NN) {
                const float* sp = stage + row * STG_LD + c4;
                float4 bb = *reinterpret_cast<const float4*>(bias + c4);
                float4 hv = ld_split4(XH, XL, (size_t)grow * DD + c4);
                float4 o;
                o.x = sp[0] + bb.x + hv.x;
                o.y = sp[1] + bb.y + hv.y;
                o.z = sp[2] + bb.z + hv.z;
                o.w = sp[3] + bb.w + hv.w;
                if (do_relu) {
                    o.x = fmaxf(o.x, 0.f); o.y = fmaxf(o.y, 0.f);
                    o.z = fmaxf(o.z, 0.f); o.w = fmaxf(o.w, 0.f);
                }
                if (f32out)
                    *reinterpret_cast<float4*>(oout + (size_t)grow * DD + c4) = o;
                if (wsel >= 0) {
                    size_t so = ((size_t)grow * DD + c4) / 4;
                    split4(o, reinterpret_cast<uint2*>(WXH) + so,
                              reinterpret_cast<uint2*>(WXL) + so);
                }
            }
        }
        __syncthreads();
    }
}

// ---------------- launch ----------------
extern "C" void kernel_launch(void* const* d_in, const int* in_sizes, int n_in,
                              void* d_out, int out_size) {
    const float* x  = (const float*)d_in[0];
    const int*   ei = (const int*)d_in[1];
    const float* Wl = (const float*)d_in[2];
    const float* bl = (const float*)d_in[3];
    const float* Wr = (const float*)d_in[4];
    const int* src = ei;
    const int* dst = ei + NE;
    float* out = (float*)d_out;

    const int SB = 1184;
    const int GATHERB = (NN * 32 + 255) / 256;   // one warp per node
    const int GB = (NN + 127) / 128;             // 782 gemm blocks

    convert_all_kernel<<<SB, 256>>>(Wl, Wr, x);  // launch 1 (weights + x split -> set0)
    hist_kernel<<<SB, 256>>>(dst);               // launch 2
    scan_kernel<<<1, 1024>>>();                  // launch 3 (re-zeros g_cnt)
    fill_kernel<<<SB, 256>>>(src, dst);          // launch 4

    // layer 0: A = [mean | set0], writes set1
    gather_f32_kernel<<<GATHERB, 256>>>(x);                          // launch 5
    sage_wmma_kernel<<<GB, 256>>>(out, bl, 0 * KK * DD, 0, 1, 1, 0); // launch 6 (ncu)

    // layer 1: A = [mean | set1], writes set0
    gather_bf16_kernel<<<GATHERB, 256>>>(1);
    sage_wmma_kernel<<<GB, 256>>>(out, bl + DD, 1 * KK * DD, 1, 0, 1, 0);

    // layer 2: A = [mean | set0], writes f32 out only
    gather_bf16_kernel<<<GATHERB, 256>>>(0);
    sage_wmma_kernel<<<GB, 256>>>(out, bl + 2 * DD, 2 * KK * DD, 0, -1, 0, 1);
}

// round 14
// speedup vs baseline: 1.3748x; 1.3748x over previous
#include <cuda_runtime.h>
#include <cuda_fp16.h>
#include <mma.h>
#include <cstdint>

using namespace nvcuda;

#define NN 100000
#define NE 1600000
#define DD 128
#define KK 256   // concat K: [mean | h]

// ---------------- static device scratch (~90MB) ---------------------------------
__device__ __half g_mh[(size_t)NN * DD];    // fp16 mean
__device__ __half g_x0[(size_t)NN * DD];    // fp16 activations, ping
__device__ __half g_x1[(size_t)NN * DD];    // fp16 activations, pong
__device__ __half g_W[3 * KK * DD];         // fp16 concat weights [Wl ; Wr+I]
// CSR (g_cnt statically zero-initialized; scan_kernel re-zeros it each launch)
__device__ int g_cnt[NN];
__device__ int g_rowptr[NN + 1];
__device__ int g_cursor[NN];
__device__ int g_csrc[NE];

// ---------------- helpers ----------------
__device__ __forceinline__ float4 ld_h4(const __half* X, size_t off) {
    uint2 u = *reinterpret_cast<const uint2*>(X + off);
    float2 f01 = __half22float2(*reinterpret_cast<__half2*>(&u.x));
    float2 f23 = __half22float2(*reinterpret_cast<__half2*>(&u.y));
    return make_float4(f01.x, f01.y, f23.x, f23.y);
}

__device__ __forceinline__ uint2 f4_to_h4(const float4 v) {
    __half2 h01 = __floats2half2_rn(v.x, v.y);
    __half2 h23 = __floats2half2_rn(v.z, v.w);
    uint2 u;
    u.x = *reinterpret_cast<unsigned*>(&h01);
    u.y = *reinterpret_cast<unsigned*>(&h23);
    return u;
}

// ---------------- conversion: weights (+I fold) and x -> fp16 set 0 -------------
__global__ void convert_all_kernel(const float* __restrict__ Wl,
                                   const float* __restrict__ Wr,
                                   const float* __restrict__ x) {
    int idx = blockIdx.x * blockDim.x + threadIdx.x;
    const int nw = 3 * KK * DD;
    if (idx < nw) {
        int l = idx / (KK * DD);
        int r = idx - l * (KK * DD);
        int k = r / DD;
        int n = r - k * DD;
        float v;
        if (k < DD) {
            v = Wl[(size_t)l * DD * DD + k * DD + n];
        } else {
            v = Wr[(size_t)l * DD * DD + (k - DD) * DD + n];
            if (k - DD == n) v += 1.0f;       // fold residual: h @ (Wr + I)
        }
        g_W[idx] = __float2half_rn(v);
    }
    size_t n4 = (size_t)NN * DD / 4;
    size_t stride = (size_t)gridDim.x * blockDim.x;
    for (size_t v = (size_t)idx; v < n4; v += stride) {
        float4 f = reinterpret_cast<const float4*>(x)[v];
        reinterpret_cast<uint2*>(g_x0)[v] = f4_to_h4(f);
    }
}

// ---------------- CSR build ----------------
__global__ void hist_kernel(const int* __restrict__ dst) {
    int stride = gridDim.x * blockDim.x;
    for (int e = blockIdx.x * blockDim.x + threadIdx.x; e < NE; e += stride)
        atomicAdd(&g_cnt[dst[e]], 1);
}

__global__ void scan_kernel() {
    __shared__ int sh[1024];
    const int t = threadIdx.x;
    const int chunk = (NN + 1023) / 1024;
    int start = t * chunk;
    int end   = min(start + chunk, NN);
    int s = 0;
    for (int j = start; j < end; j++) {
        g_rowptr[j] = s;
        s += g_cnt[j];
        g_cnt[j] = 0;        // restore for next launch
    }
    sh[t] = s;
    __syncthreads();
    for (int off = 1; off < 1024; off <<= 1) {
        int v = (t >= off) ? sh[t - off] : 0;
        __syncthreads();
        sh[t] += v;
        __syncthreads();
    }
    int excl = (t == 0) ? 0 : sh[t - 1];
    for (int j = start; j < end; j++) {
        int v = g_rowptr[j] + excl;
        g_rowptr[j] = v;
        g_cursor[j] = v;
    }
    if (t == 0) g_rowptr[NN] = NE;
}

__global__ void fill_kernel(const int* __restrict__ src, const int* __restrict__ dst) {
    int stride = gridDim.x * blockDim.x;
    for (int e = blockIdx.x * blockDim.x + threadIdx.x; e < NE; e += stride) {
        int p = atomicAdd(&g_cursor[dst[e]], 1);
        g_csrc[p] = src[e];
    }
}

// ---------------- gather: one warp per node (CSR), fp16 rows, MLP-4 ------------
__global__ void gather_kernel(int sel) {
    const __half* __restrict__ X = sel ? g_x1 : g_x0;
    int n = (blockIdx.x * blockDim.x + threadIdx.x) >> 5;
    if (n >= NN) return;
    int lane = threadIdx.x & 31;
    int beg = g_rowptr[n];
    int end = g_rowptr[n + 1];
    float4 a0 = make_float4(0.f, 0.f, 0.f, 0.f);
    float4 a1 = a0, a2 = a0, a3 = a0;
    int e = beg;
    for (; e + 4 <= end; e += 4) {
        int s0 = __ldg(&g_csrc[e + 0]);
        int s1 = __ldg(&g_csrc[e + 1]);
        int s2 = __ldg(&g_csrc[e + 2]);
        int s3 = __ldg(&g_csrc[e + 3]);
        float4 v0 = ld_h4(X, (size_t)s0 * DD + lane * 4);
        float4 v1 = ld_h4(X, (size_t)s1 * DD + lane * 4);
        float4 v2 = ld_h4(X, (size_t)s2 * DD + lane * 4);
        float4 v3 = ld_h4(X, (size_t)s3 * DD + lane * 4);
        a0.x += v0.x; a0.y += v0.y; a0.z += v0.z; a0.w += v0.w;
        a1.x += v1.x; a1.y += v1.y; a1.z += v1.z; a1.w += v1.w;
        a2.x += v2.x; a2.y += v2.y; a2.z += v2.z; a2.w += v2.w;
        a3.x += v3.x; a3.y += v3.y; a3.z += v3.z; a3.w += v3.w;
    }
    for (; e < end; e++) {
        int s = __ldg(&g_csrc[e]);
        float4 v = ld_h4(X, (size_t)s * DD + lane * 4);
        a0.x += v.x; a0.y += v.y; a0.z += v.z; a0.w += v.w;
    }
    float4 a;
    a.x = (a0.x + a1.x) + (a2.x + a3.x);
    a.y = (a0.y + a1.y) + (a2.y + a3.y);
    a.z = (a0.z + a1.z) + (a2.z + a3.z);
    a.w = (a0.w + a1.w) + (a2.w + a3.w);
    float invd = 1.f / fmaxf((float)(end - beg), 1.f);
    a.x *= invd; a.y *= invd; a.z *= invd; a.w *= invd;
    reinterpret_cast<uint2*>(g_mh)[((size_t)n * DD + lane * 4) / 4] = f4_to_h4(a);
}

// ---------------- fp16 tensor-core GEMM: out = [mean|h] @ [Wl;Wr+I] + b --------
// Block 128x128, K=256, BK=64, single volume. 8 warps as 2(m)x4(n).
#define ALD 72
#define BLD 136
#define SM_A_BYTES (128 * ALD * 2)     // 18432
#define SM_B_BYTES (64 * BLD * 2)      // 17408
#define SM_TOT (SM_A_BYTES + SM_B_BYTES)  // 35840 (>= 64*132*4 epilogue stage)
#define STG_LD 132

__global__ __launch_bounds__(256, 2)
void sage_gemm_kernel(float* __restrict__ oout,
                      const float* __restrict__ bias,
                      int lw, int rsel, int wsel, int do_relu, int f32out) {
    const __half* __restrict__ XH = rsel ? g_x1 : g_x0;
    __half* __restrict__ WX = (wsel == 1) ? g_x1 : g_x0;

    __shared__ __align__(16) char smem[SM_TOT];
    __half* As = reinterpret_cast<__half*>(smem);
    __half* Bs = reinterpret_cast<__half*>(smem + SM_A_BYTES);
    float* stage = reinterpret_cast<float*>(smem);   // epilogue alias [64][132]

    const int tid = threadIdx.x;
    const int w  = tid >> 5;
    const int wm = w >> 2;              // 0..1 : 64-row group
    const int wn = w & 3;               // 0..3 : 32-col group
    const int rowBase = blockIdx.x * 128;

    // A copy: row = tid>>1 (0..127), 32 cols per thread (4 x 16B)
    const int ar = tid >> 1;
    const int ac = (tid & 1) * 32;
    const int aclamp = min(rowBase + ar, NN - 1);
    // B copy: kr = tid>>2 (0..63), 32 n per thread (4 x 16B)
    const int bkr = tid >> 2;
    const int bnc = (tid & 3) * 32;

    wmma::fragment<wmma::accumulator, 16, 16, 16, float> acc[4][2];
    #pragma unroll
    for (int i = 0; i < 4; i++)
        #pragma unroll
        for (int j = 0; j < 2; j++) wmma::fill_fragment(acc[i][j], 0.f);

    for (int kb = 0; kb < 4; kb++) {
        // ---- A tile: 128 rows x 64 k fp16 ----
        const __half* A = (kb < 2) ? g_mh : XH;
        int k0 = (kb & 1) * 64 + ac;
        #pragma unroll
        for (int q = 0; q < 4; q++) {
            *reinterpret_cast<uint4*>(As + ar * ALD + ac + q * 8) =
                *reinterpret_cast<const uint4*>(A + (size_t)aclamp * DD + k0 + q * 8);
        }
        // ---- B tile: 64 k x 128 n fp16 ----
        #pragma unroll
        for (int q = 0; q < 4; q++) {
            *reinterpret_cast<uint4*>(Bs + bkr * BLD + bnc + q * 8) =
                *reinterpret_cast<const uint4*>(
                    g_W + (size_t)lw + (size_t)(kb * 64 + bkr) * DD + bnc + q * 8);
        }
        __syncthreads();

        #pragma unroll
        for (int kk = 0; kk < 64; kk += 16) {
            wmma::fragment<wmma::matrix_b, 16, 16, 16, __half, wmma::row_major> bf[2];
            #pragma unroll
            for (int j = 0; j < 2; j++)
                wmma::load_matrix_sync(bf[j], Bs + kk * BLD + wn * 32 + j * 16, BLD);
            #pragma unroll
            for (int i = 0; i < 4; i++) {
                wmma::fragment<wmma::matrix_a, 16, 16, 16, __half, wmma::row_major> af;
                wmma::load_matrix_sync(af, As + (wm * 64 + i * 16) * ALD + kk, ALD);
                #pragma unroll
                for (int j = 0; j < 2; j++)
                    wmma::mma_sync(acc[i][j], af, bf[j], acc[i][j]);
            }
        }
        __syncthreads();
    }

    // ---- epilogue in two 64-row halves (stage aliases the tile smem) ----
    #pragma unroll
    for (int ph = 0; ph < 2; ph++) {
        if (wm == ph) {
            #pragma unroll
            for (int i = 0; i < 4; i++)
                #pragma unroll
                for (int j = 0; j < 2; j++)
                    wmma::store_matrix_sync(stage + (i * 16) * STG_LD + wn * 32 + j * 16,
                                            acc[i][j], STG_LD, wmma::mem_row_major);
        }
        __syncthreads();
        #pragma unroll
        for (int it = 0; it < 8; it++) {
            int idx = it * 256 + tid;          // 0..2047
            int row = idx >> 5;                // 0..63
            int c4  = (idx & 31) * 4;          // 0..124
            int grow = rowBase + ph * 64 + row;
            if (grow < NN) {
                const float* sp = stage + row * STG_LD + c4;
                float4 bb = *reinterpret_cast<const float4*>(bias + c4);
                float4 o;
                o.x = sp[0] + bb.x;
                o.y = sp[1] + bb.y;
                o.z = sp[2] + bb.z;
                o.w = sp[3] + bb.w;
                if (do_relu) {
                    o.x = fmaxf(o.x, 0.f); o.y = fmaxf(o.y, 0.f);
                    o.z = fmaxf(o.z, 0.f); o.w = fmaxf(o.w, 0.f);
                }
                if (f32out)
                    *reinterpret_cast<float4*>(oout + (size_t)grow * DD + c4) = o;
                if (wsel >= 0)
                    reinterpret_cast<uint2*>(WX)[((size_t)grow * DD + c4) / 4] =
                        f4_to_h4(o);
            }
        }
        __syncthreads();
    }
}

// ---------------- launch ----------------
extern "C" void kernel_launch(void* const* d_in, const int* in_sizes, int n_in,
                              void* d_out, int out_size) {
    const float* x  = (const float*)d_in[0];
    const int*   ei = (const int*)d_in[1];
    const float* Wl = (const float*)d_in[2];
    const float* bl = (const float*)d_in[3];
    const float* Wr = (const float*)d_in[4];
    const int* src = ei;
    const int* dst = ei + NE;
    float* out = (float*)d_out;

    const int SB = 1184;
    const int GATHERB = (NN * 32 + 255) / 256;   // one warp per node
    const int GB = (NN + 127) / 128;             // 782 gemm blocks

    convert_all_kernel<<<SB, 256>>>(Wl, Wr, x);  // launch 1
    hist_kernel<<<SB, 256>>>(dst);               // launch 2
    scan_kernel<<<1, 1024>>>();                  // launch 3
    fill_kernel<<<SB, 256>>>(src, dst);          // launch 4

    // layer 0: A = [mean | x0], writes x1 (relu)
    gather_kernel<<<GATHERB, 256>>>(0);                                  // launch 5
    sage_gemm_kernel<<<GB, 256>>>(out, bl, 0 * KK * DD, 0, 1, 1, 0);     // launch 6

    // layer 1: A = [mean | x1], writes x0 (relu)
    gather_kernel<<<GATHERB, 256>>>(1);
    sage_gemm_kernel<<<GB, 256>>>(out, bl + DD, 1 * KK * DD, 1, 0, 1, 0);

    // layer 2: A = [mean | x0], writes f32 out only (no relu)
    gather_kernel<<<GATHERB, 256>>>(0);
    sage_gemm_kernel<<<GB, 256>>>(out, bl + 2 * DD, 2 * KK * DD, 0, -1, 0, 1);
}

// round 15
// speedup vs baseline: 1.4169x; 1.0306x over previous
#include <cuda_runtime.h>
#include <cuda_fp16.h>
#include <cuda_pipeline.h>
#include <mma.h>
#include <cstdint>

using namespace nvcuda;

#define NN 100000
#define NE 1600000
#define DD 128
#define KK 256   // concat K: [mean | h]

// ---------------- static device scratch (~90MB) ---------------------------------
__device__ __half g_mh[(size_t)NN * DD];    // fp16 mean
__device__ __half g_x0[(size_t)NN * DD];    // fp16 activations, ping
__device__ __half g_x1[(size_t)NN * DD];    // fp16 activations, pong
__device__ __half g_W[3 * KK * DD];         // fp16 concat weights [Wl ; Wr+I]
// CSR (g_cnt statically zero-initialized; scan_kernel re-zeros it each launch)
__device__ int g_cnt[NN];
__device__ int g_rowptr[NN + 1];
__device__ int g_cursor[NN];
__device__ int g_csrc[NE];

// ---------------- helpers ----------------
__device__ __forceinline__ float4 ld_h4(const __half* X, size_t off) {
    uint2 u = *reinterpret_cast<const uint2*>(X + off);
    float2 f01 = __half22float2(*reinterpret_cast<__half2*>(&u.x));
    float2 f23 = __half22float2(*reinterpret_cast<__half2*>(&u.y));
    return make_float4(f01.x, f01.y, f23.x, f23.y);
}

__device__ __forceinline__ uint2 f4_to_h4(const float4 v) {
    __half2 h01 = __floats2half2_rn(v.x, v.y);
    __half2 h23 = __floats2half2_rn(v.z, v.w);
    uint2 u;
    u.x = *reinterpret_cast<unsigned*>(&h01);
    u.y = *reinterpret_cast<unsigned*>(&h23);
    return u;
}

// ---------------- conversion: weights (+I fold) and x -> fp16 set 0 -------------
__global__ void convert_all_kernel(const float* __restrict__ Wl,
                                   const float* __restrict__ Wr,
                                   const float* __restrict__ x) {
    int idx = blockIdx.x * blockDim.x + threadIdx.x;
    const int nw = 3 * KK * DD;
    if (idx < nw) {
        int l = idx / (KK * DD);
        int r = idx - l * (KK * DD);
        int k = r / DD;
        int n = r - k * DD;
        float v;
        if (k < DD) {
            v = Wl[(size_t)l * DD * DD + k * DD + n];
        } else {
            v = Wr[(size_t)l * DD * DD + (k - DD) * DD + n];
            if (k - DD == n) v += 1.0f;       // fold residual: h @ (Wr + I)
        }
        g_W[idx] = __float2half_rn(v);
    }
    size_t n4 = (size_t)NN * DD / 4;
    size_t stride = (size_t)gridDim.x * blockDim.x;
    for (size_t v = (size_t)idx; v < n4; v += stride) {
        float4 f = reinterpret_cast<const float4*>(x)[v];
        reinterpret_cast<uint2*>(g_x0)[v] = f4_to_h4(f);
    }
}

// ---------------- CSR build ----------------
__global__ void hist_kernel(const int* __restrict__ dst) {
    int stride = gridDim.x * blockDim.x;
    for (int e = blockIdx.x * blockDim.x + threadIdx.x; e < NE; e += stride)
        atomicAdd(&g_cnt[dst[e]], 1);
}

__global__ void scan_kernel() {
    __shared__ int sh[1024];
    const int t = threadIdx.x;
    const int chunk = (NN + 1023) / 1024;
    int start = t * chunk;
    int end   = min(start + chunk, NN);
    int s = 0;
    for (int j = start; j < end; j++) {
        g_rowptr[j] = s;
        s += g_cnt[j];
        g_cnt[j] = 0;        // restore for next launch
    }
    sh[t] = s;
    __syncthreads();
    for (int off = 1; off < 1024; off <<= 1) {
        int v = (t >= off) ? sh[t - off] : 0;
        __syncthreads();
        sh[t] += v;
        __syncthreads();
    }
    int excl = (t == 0) ? 0 : sh[t - 1];
    for (int j = start; j < end; j++) {
        int v = g_rowptr[j] + excl;
        g_rowptr[j] = v;
        g_cursor[j] = v;
    }
    if (t == 0) g_rowptr[NN] = NE;
}

__global__ void fill_kernel(const int* __restrict__ src, const int* __restrict__ dst) {
    int stride = gridDim.x * blockDim.x;
    for (int e = blockIdx.x * blockDim.x + threadIdx.x; e < NE; e += stride) {
        int p = atomicAdd(&g_cursor[dst[e]], 1);
        g_csrc[p] = src[e];
    }
}

// ---------------- gather: one warp per node (CSR), fp16 rows, MLP-4 ------------
__global__ void gather_kernel(int sel) {
    const __half* __restrict__ X = sel ? g_x1 : g_x0;
    int n = (blockIdx.x * blockDim.x + threadIdx.x) >> 5;
    if (n >= NN) return;
    int lane = threadIdx.x & 31;
    int beg = g_rowptr[n];
    int end = g_rowptr[n + 1];
    float4 a0 = make_float4(0.f, 0.f, 0.f, 0.f);
    float4 a1 = a0, a2 = a0, a3 = a0;
    int e = beg;
    for (; e + 4 <= end; e += 4) {
        int s0 = __ldg(&g_csrc[e + 0]);
        int s1 = __ldg(&g_csrc[e + 1]);
        int s2 = __ldg(&g_csrc[e + 2]);
        int s3 = __ldg(&g_csrc[e + 3]);
        float4 v0 = ld_h4(X, (size_t)s0 * DD + lane * 4);
        float4 v1 = ld_h4(X, (size_t)s1 * DD + lane * 4);
        float4 v2 = ld_h4(X, (size_t)s2 * DD + lane * 4);
        float4 v3 = ld_h4(X, (size_t)s3 * DD + lane * 4);
        a0.x += v0.x; a0.y += v0.y; a0.z += v0.z; a0.w += v0.w;
        a1.x += v1.x; a1.y += v1.y; a1.z += v1.z; a1.w += v1.w;
        a2.x += v2.x; a2.y += v2.y; a2.z += v2.z; a2.w += v2.w;
        a3.x += v3.x; a3.y += v3.y; a3.z += v3.z; a3.w += v3.w;
    }
    for (; e < end; e++) {
        int s = __ldg(&g_csrc[e]);
        float4 v = ld_h4(X, (size_t)s * DD + lane * 4);
        a0.x += v.x; a0.y += v.y; a0.z += v.z; a0.w += v.w;
    }
    float4 a;
    a.x = (a0.x + a1.x) + (a2.x + a3.x);
    a.y = (a0.y + a1.y) + (a2.y + a3.y);
    a.z = (a0.z + a1.z) + (a2.z + a3.z);
    a.w = (a0.w + a1.w) + (a2.w + a3.w);
    float invd = 1.f / fmaxf((float)(end - beg), 1.f);
    a.x *= invd; a.y *= invd; a.z *= invd; a.w *= invd;
    reinterpret_cast<uint2*>(g_mh)[((size_t)n * DD + lane * 4) / 4] = f4_to_h4(a);
}

// ---------------- fp16 tensor-core GEMM: cp.async 2-stage, BK=32 ---------------
// out = [mean|h] @ [Wl;Wr+I] + b.  Block 128x128, 8 warps as 2(m)x4(n).
#define ALD 40
#define BLD 136
#define ST_A_BYTES (128 * ALD * 2)         // 10240
#define ST_B_BYTES (32 * BLD * 2)          // 8704
#define STAGE_BYTES (ST_A_BYTES + ST_B_BYTES)  // 18944
#define SM_TOT (2 * STAGE_BYTES)           // 37888 (>= 64*132*4 epilogue stage)
#define STG_LD 132

__global__ __launch_bounds__(256, 2)
void sage_gemm_kernel(float* __restrict__ oout,
                      const float* __restrict__ bias,
                      int lw, int rsel, int wsel, int do_relu, int f32out) {
    const __half* __restrict__ XH = rsel ? g_x1 : g_x0;
    __half* __restrict__ WX = (wsel == 1) ? g_x1 : g_x0;

    __shared__ __align__(16) char smem[SM_TOT];
    float* stage = reinterpret_cast<float*>(smem);   // epilogue alias [64][132]

    const int tid = threadIdx.x;
    const int w  = tid >> 5;
    const int wm = w >> 2;              // 0..1 : 64-row group
    const int wn = w & 3;               // 0..3 : 32-col group
    const int rowBase = blockIdx.x * 128;

    // A copy: row = tid>>1 (0..127), 16 halves per thread (2 x 16B)
    const int ar = tid >> 1;
    const int ac = (tid & 1) * 16;
    const int aclamp = min(rowBase + ar, NN - 1);
    // B copy: kr = tid>>3 (0..31), 16 halves per thread (2 x 16B)
    const int bkr = tid >> 3;
    const int bnc = (tid & 7) * 16;

    wmma::fragment<wmma::accumulator, 16, 16, 16, float> acc[4][2];
    #pragma unroll
    for (int i = 0; i < 4; i++)
        #pragma unroll
        for (int j = 0; j < 2; j++) wmma::fill_fragment(acc[i][j], 0.f);

    auto copy_stage = [&](int kb, int b) {
        char* base = smem + b * STAGE_BYTES;
        __half* As = reinterpret_cast<__half*>(base);
        __half* Bs = reinterpret_cast<__half*>(base + ST_A_BYTES);
        const __half* A = (kb < 4) ? g_mh : XH;
        int k0 = (kb & 3) * 32;
        #pragma unroll
        for (int q = 0; q < 2; q++)
            __pipeline_memcpy_async(As + ar * ALD + ac + q * 8,
                                    A + (size_t)aclamp * DD + k0 + ac + q * 8, 16);
        #pragma unroll
        for (int q = 0; q < 2; q++)
            __pipeline_memcpy_async(Bs + bkr * BLD + bnc + q * 8,
                                    g_W + (size_t)lw + (size_t)(kb * 32 + bkr) * DD
                                        + bnc + q * 8, 16);
    };

    copy_stage(0, 0);
    __pipeline_commit();

    for (int kb = 0; kb < 8; kb++) {
        if (kb < 7) {
            copy_stage(kb + 1, (kb + 1) & 1);   // issue next BEFORE waiting
            __pipeline_commit();
            __pipeline_wait_prior(1);           // stage kb landed
        } else {
            __pipeline_wait_prior(0);
        }
        __syncthreads();

        char* base = smem + (kb & 1) * STAGE_BYTES;
        __half* As = reinterpret_cast<__half*>(base);
        __half* Bs = reinterpret_cast<__half*>(base + ST_A_BYTES);

        #pragma unroll
        for (int kk = 0; kk < 32; kk += 16) {
            wmma::fragment<wmma::matrix_b, 16, 16, 16, __half, wmma::row_major> bf[2];
            #pragma unroll
            for (int j = 0; j < 2; j++)
                wmma::load_matrix_sync(bf[j], Bs + kk * BLD + wn * 32 + j * 16, BLD);
            #pragma unroll
            for (int i = 0; i < 4; i++) {
                wmma::fragment<wmma::matrix_a, 16, 16, 16, __half, wmma::row_major> af;
                wmma::load_matrix_sync(af, As + (wm * 64 + i * 16) * ALD + kk, ALD);
                #pragma unroll
                for (int j = 0; j < 2; j++)
                    wmma::mma_sync(acc[i][j], af, bf[j], acc[i][j]);
            }
        }
        __syncthreads();
    }

    // ---- epilogue in two 64-row halves (stage aliases the tile smem) ----
    #pragma unroll
    for (int ph = 0; ph < 2; ph++) {
        if (wm == ph) {
            #pragma unroll
            for (int i = 0; i < 4; i++)
                #pragma unroll
                for (int j = 0; j < 2; j++)
                    wmma::store_matrix_sync(stage + (i * 16) * STG_LD + wn * 32 + j * 16,
                                            acc[i][j], STG_LD, wmma::mem_row_major);
        }
        __syncthreads();
        #pragma unroll
        for (int it = 0; it < 8; it++) {
            int idx = it * 256 + tid;          // 0..2047
            int row = idx >> 5;                // 0..63
            int c4  = (idx & 31) * 4;          // 0..124
            int grow = rowBase + ph * 64 + row;
            if (grow < NN) {
                const float* sp = stage + row * STG_LD + c4;
                float4 bb = *reinterpret_cast<const float4*>(bias + c4);
                float4 o;
                o.x = sp[0] + bb.x;
                o.y = sp[1] + bb.y;
                o.z = sp[2] + bb.z;
                o.w = sp[3] + bb.w;
                if (do_relu) {
                    o.x = fmaxf(o.x, 0.f); o.y = fmaxf(o.y, 0.f);
                    o.z = fmaxf(o.z, 0.f); o.w = fmaxf(o.w, 0.f);
                }
                if (f32out)
                    *reinterpret_cast<float4*>(oout + (size_t)grow * DD + c4) = o;
                if (wsel >= 0)
                    reinterpret_cast<uint2*>(WX)[((size_t)grow * DD + c4) / 4] =
                        f4_to_h4(o);
            }
        }
        __syncthreads();
    }
}

// ---------------- launch ----------------
extern "C" void kernel_launch(void* const* d_in, const int* in_sizes, int n_in,
                              void* d_out, int out_size) {
    const float* x  = (const float*)d_in[0];
    const int*   ei = (const int*)d_in[1];
    const float* Wl = (const float*)d_in[2];
    const float* bl = (const float*)d_in[3];
    const float* Wr = (const float*)d_in[4];
    const int* src = ei;
    const int* dst = ei + NE;
    float* out = (float*)d_out;

    const int SB = 1184;
    const int GATHERB = (NN * 32 + 255) / 256;   // one warp per node
    const int GB = (NN + 127) / 128;             // 782 gemm blocks

    convert_all_kernel<<<SB, 256>>>(Wl, Wr, x);  // launch 1
    hist_kernel<<<SB, 256>>>(dst);               // launch 2
    scan_kernel<<<1, 1024>>>();                  // launch 3
    fill_kernel<<<SB, 256>>>(src, dst);          // launch 4

    // layer 0: A = [mean | x0], writes x1 (relu)
    gather_kernel<<<GATHERB, 256>>>(0);                                  // launch 5
    sage_gemm_kernel<<<GB, 256>>>(out, bl, 0 * KK * DD, 0, 1, 1, 0);     // launch 6

    // layer 1: A = [mean | x1], writes x0 (relu)
    gather_kernel<<<GATHERB, 256>>>(1);
    sage_gemm_kernel<<<GB, 256>>>(out, bl + DD, 1 * KK * DD, 1, 0, 1, 0);

    // layer 2: A = [mean | x0], writes f32 out only (no relu)
    gather_kernel<<<GATHERB, 256>>>(0);
    sage_gemm_kernel<<<GB, 256>>>(out, bl + 2 * DD, 2 * KK * DD, 0, -1, 0, 1);
}